// round 1
// baseline (speedup 1.0000x reference)
#include <cuda_runtime.h>
#include <cuda_bf16.h>
#include <cstddef>

#define RR   7
#define KS   15          // kernel side = 2R+1
#define NK   (KS*KS)     // 225
#define BATCH 8
#define HI   512
#define WI   512
#define HO   256         // HI/2 (stride 2)
#define WO   256
#define TX   64          // output tile width per block
#define TY   16          // output tile height per block
#define SW   (TX + 2*RR) // 78
#define SH   (TY + 2*RR) // 30

__global__ __launch_bounds__(256, 4)
void adj_equality_kernel(const float* __restrict__ in, float* __restrict__ out)
{
    __shared__ float tile[SH][SW];

    const int bx = blockIdx.x;          // 0..3   (WO/TX)
    const int by = blockIdx.y;          // 0..15  (HO/TY)
    const int b  = blockIdx.z;          // 0..7
    const int tid = threadIdx.x;        // 0..255

    const int x0 = bx * TX;
    const int y0 = by * TY;

    // ---- Load tile + halo (zero padding outside), downsampling stride-2 on the fly ----
    const float* __restrict__ inb = in + (size_t)b * HI * WI;
    #pragma unroll
    for (int i = tid; i < SH * SW; i += 256) {
        const int r = i / SW;
        const int c = i - r * SW;
        const int gy = y0 + r - RR;     // downsampled coords
        const int gx = x0 + c - RR;
        float v = 0.0f;
        if (gy >= 0 && gy < HO && gx >= 0 && gx < WO)
            v = inb[(size_t)(gy * 2) * WI + (size_t)(gx * 2)];
        tile[r][c] = v;
    }
    __syncthreads();

    // ---- Each thread owns 4 contiguous output columns ----
    const int tx = tid & 15;            // 0..15
    const int ty = tid >> 4;            // 0..15
    const int lx = tx * 4;              // 0..60 local x
    const int ly = ty;                  // local y

    const float c0 = tile[ly + RR][lx + RR + 0];
    const float c1 = tile[ly + RR][lx + RR + 1];
    const float c2 = tile[ly + RR][lx + RR + 2];
    const float c3 = tile[ly + RR][lx + RR + 3];

    const int oy = y0 + ly;
    const int ox = x0 + lx;
    float* __restrict__ outb = out + (size_t)b * NK * HO * WO
                                   + (size_t)oy * WO + ox;

    // dy rolled (keeps body in L0 I$), dx fully unrolled (static reg indexing)
    for (int dy = 0; dy < KS; ++dy) {
        // slide-window register cache: 18 consecutive floats of this row
        float nb[KS + 3];
        #pragma unroll
        for (int j = 0; j < KS + 3; ++j)
            nb[j] = tile[ly + dy][lx + j];

        float* __restrict__ orow = outb + (size_t)(dy * KS) * HO * WO;
        #pragma unroll
        for (int dx = 0; dx < KS; ++dx) {
            float4 v;
            v.x = (nb[dx + 0] == c0) ? 1.0f : 0.0f;
            v.y = (nb[dx + 1] == c1) ? 1.0f : 0.0f;
            v.z = (nb[dx + 2] == c2) ? 1.0f : 0.0f;
            v.w = (nb[dx + 3] == c3) ? 1.0f : 0.0f;
            *reinterpret_cast<float4*>(orow + (size_t)dx * HO * WO) = v;
        }
    }
}

extern "C" void kernel_launch(void* const* d_in, const int* in_sizes, int n_in,
                              void* d_out, int out_size)
{
    const float* segments = (const float*)d_in[0];
    float* out = (float*)d_out;

    dim3 grid(WO / TX, HO / TY, BATCH);   // (4, 16, 8) = 512 blocks
    dim3 block(256);
    adj_equality_kernel<<<grid, block>>>(segments, out);
}